// round 2
// baseline (speedup 1.0000x reference)
#include <cuda_runtime.h>
#include <math.h>

#define HH 256
#define WW 256
#define HWN 65536
#define GG 8
#define CGC 8

// ---------------- scratch (device globals; no allocation allowed) ----------------
__device__ float g_t0[64 * HWN];
__device__ float g_t1[64 * HWN];
__device__ float g_conv3[216 * HWN];
__device__ float g_cat[128 * HWN];
__device__ float g_wT[9 * 64 * 64];

// ---------------- direct 3x3 conv, pad 1, optional leaky-relu(0.1) ----------------
// Block: 128 threads (32 x, 4 y). Tile: 32 wide x 16 high. 8 output channels / block.
// Each thread: 4 pixels (rows ty, ty+4, ty+8, ty+12) x 8 couts = 32 accumulators.
template <int CIN, bool LRELU>
__global__ __launch_bounds__(128) void conv3x3_kernel(
    const float* __restrict__ in, const float* __restrict__ wgt,
    const float* __restrict__ bias, float* __restrict__ out)
{
    __shared__ float s_in[2][18][34];
    __shared__ float s_w[CIN][8][9];

    const int tid = threadIdx.x;
    const int tx = tid & 31;
    const int ty = tid >> 5;          // 0..3
    const int x0 = blockIdx.x * 32;
    const int y0 = blockIdx.y * 16;
    const int coB = blockIdx.z * 8;

    // preload all weights for this block's 8 output channels
    for (int i = tid; i < CIN * 8 * 9; i += 128) {
        int co = i / (CIN * 9);
        int r = i - co * (CIN * 9);
        int ci = r / 9;
        int k = r - ci * 9;
        s_w[ci][co][k] = wgt[(size_t)(coB + co) * (CIN * 9) + r];
    }
    // load input tile for ci = 0
    for (int i = tid; i < 18 * 34; i += 128) {
        int r = i / 34, c = i - r * 34;
        int gy = y0 - 1 + r, gx = x0 - 1 + c;
        float v = 0.f;
        if (gy >= 0 && gy < HH && gx >= 0 && gx < WW) v = in[gy * WW + gx];
        s_in[0][r][c] = v;
    }
    __syncthreads();

    float acc[4][8];
#pragma unroll
    for (int p = 0; p < 4; p++)
#pragma unroll
        for (int o = 0; o < 8; o++) acc[p][o] = 0.f;

    for (int ci = 0; ci < CIN; ci++) {
        const int pb = ci & 1;
        // prefetch next channel tile into the other buffer
        if (ci + 1 < CIN) {
            const float* ip = in + (size_t)(ci + 1) * HWN;
            for (int i = tid; i < 18 * 34; i += 128) {
                int r = i / 34, c = i - r * 34;
                int gy = y0 - 1 + r, gx = x0 - 1 + c;
                float v = 0.f;
                if (gy >= 0 && gy < HH && gx >= 0 && gx < WW) v = ip[gy * WW + gx];
                s_in[1 - pb][r][c] = v;
            }
        }
        // gather input neighborhood into registers
        float v[4][3][3];
#pragma unroll
        for (int p = 0; p < 4; p++) {
            int ly = ty + 4 * p;
#pragma unroll
            for (int r = 0; r < 3; r++)
#pragma unroll
                for (int c = 0; c < 3; c++) v[p][r][c] = s_in[pb][ly + r][tx + c];
        }
#pragma unroll
        for (int o = 0; o < 8; o++) {
            float wr[9];
#pragma unroll
            for (int k = 0; k < 9; k++) wr[k] = s_w[ci][o][k];
#pragma unroll
            for (int p = 0; p < 4; p++) {
                float a = acc[p][o];
                a = fmaf(v[p][0][0], wr[0], a);
                a = fmaf(v[p][0][1], wr[1], a);
                a = fmaf(v[p][0][2], wr[2], a);
                a = fmaf(v[p][1][0], wr[3], a);
                a = fmaf(v[p][1][1], wr[4], a);
                a = fmaf(v[p][1][2], wr[5], a);
                a = fmaf(v[p][2][0], wr[6], a);
                a = fmaf(v[p][2][1], wr[7], a);
                a = fmaf(v[p][2][2], wr[8], a);
                acc[p][o] = a;
            }
        }
        __syncthreads();
    }

#pragma unroll
    for (int o = 0; o < 8; o++) {
        float bb = bias[coB + o];
#pragma unroll
        for (int p = 0; p < 4; p++) {
            float r = acc[p][o] + bb;
            if (LRELU) r = (r >= 0.f) ? r : 0.1f * r;
            out[(size_t)(coB + o) * HWN + (size_t)(y0 + ty + 4 * p) * WW + x0 + tx] = r;
        }
    }
}

// ---------------- weight transpose for mdcn: wT[k][cin][o] = w[o][cin][k] ----------
__global__ void transpose_w_kernel(const float* __restrict__ wsrc, float* __restrict__ wT)
{
    int i = blockIdx.x * 256 + threadIdx.x;  // 9*64*64 = 36864
    if (i < 9 * 4096) {
        int k = i / 4096;
        int r = i - k * 4096;
        int ci = r >> 6;
        int o = r & 63;
        wT[i] = wsrc[(size_t)(o * 64 + ci) * 9 + k];
    }
}

// ---------------- modulated deformable conv (fused offset transform) --------------
// One thread per pixel; 64 fp32 accumulators (all output channels).
// Offsets/mask read straight from the raw conv3 output: off = 10*tanh(.) + flow_rev, mask = sigmoid(.)
__global__ __launch_bounds__(256) void mdcn_kernel(
    const float* __restrict__ x,     // [64, H, W] feature
    const float* __restrict__ co,    // [216, H, W] offset-net raw output
    const float* __restrict__ flow,  // [2, H, W]
    const float* __restrict__ wT,    // [9, 64, 64] (k, cin, o)
    const float* __restrict__ bias,  // [64]
    float* __restrict__ out)         // [64, H, W]
{
    __shared__ __align__(16) float s_w[4096];
    const int tid = threadIdx.x;
    const int px = blockIdx.x * 32 + (tid & 31);
    const int pyi = blockIdx.y * 8 + (tid >> 5);
    const int pix = pyi * WW + px;

    const float f0 = flow[pix];        // flow channel 0
    const float f1 = flow[HWN + pix];  // flow channel 1

    float acc[64];
#pragma unroll
    for (int o = 0; o < 64; o++) acc[o] = 0.f;

#pragma unroll 1
    for (int k = 0; k < 9; k++) {
        __syncthreads();
        // stage this tap's weight slice [64 cin][64 o]
        {
            const float4* src = reinterpret_cast<const float4*>(wT + (size_t)k * 4096);
            float4* dst = reinterpret_cast<float4*>(s_w);
            for (int i = tid; i < 1024; i += 256) dst[i] = src[i];
        }
        __syncthreads();
        const float kyf = (float)(k / 3 - 1);
        const float kxf = (float)(k % 3 - 1);
#pragma unroll 1
        for (int g = 0; g < GG; g++) {
            float oy = 10.f * tanhf(co[(size_t)(g * 18 + 2 * k) * HWN + pix]) + f1;
            float ox = 10.f * tanhf(co[(size_t)(g * 18 + 2 * k + 1) * HWN + pix]) + f0;
            float mr = co[(size_t)(144 + g * 9 + k) * HWN + pix];
            float mv = 1.f / (1.f + expf(-mr));

            float pyf = (float)pyi + kyf + oy;
            float pxf = (float)px + kxf + ox;
            float y0f = floorf(pyf), x0f = floorf(pxf);
            float ly = pyf - y0f, lx = pxf - x0f;
            int iy0 = (int)y0f, ix0 = (int)x0f;
            int iy1 = iy0 + 1, ix1 = ix0 + 1;
            bool vy0 = (iy0 >= 0) & (iy0 < HH);
            bool vy1 = (iy1 >= 0) & (iy1 < HH);
            bool vx0 = (ix0 >= 0) & (ix0 < WW);
            bool vx1 = (ix1 >= 0) & (ix1 < WW);
            int cy0 = min(max(iy0, 0), HH - 1), cy1 = min(max(iy1, 0), HH - 1);
            int cx0 = min(max(ix0, 0), WW - 1), cx1 = min(max(ix1, 0), WW - 1);
            float w00 = (1.f - ly) * (1.f - lx) * mv;
            float w01 = (1.f - ly) * lx * mv;
            float w10 = ly * (1.f - lx) * mv;
            float w11 = ly * lx * mv;
            int i00 = cy0 * WW + cx0, i01 = cy0 * WW + cx1;
            int i10 = cy1 * WW + cx0, i11 = cy1 * WW + cx1;

#pragma unroll 1
            for (int c = 0; c < CGC; c++) {
                const float* xc = x + (size_t)(g * 8 + c) * HWN;
                float v00 = (vy0 && vx0) ? xc[i00] : 0.f;
                float v01 = (vy0 && vx1) ? xc[i01] : 0.f;
                float v10 = (vy1 && vx0) ? xc[i10] : 0.f;
                float v11 = (vy1 && vx1) ? xc[i11] : 0.f;
                float s = v00 * w00 + v01 * w01 + v10 * w10 + v11 * w11;
                const float4* wp = reinterpret_cast<const float4*>(&s_w[(g * 8 + c) * 64]);
#pragma unroll
                for (int q = 0; q < 16; q++) {
                    float4 wv = wp[q];
                    acc[4 * q + 0] = fmaf(wv.x, s, acc[4 * q + 0]);
                    acc[4 * q + 1] = fmaf(wv.y, s, acc[4 * q + 1]);
                    acc[4 * q + 2] = fmaf(wv.z, s, acc[4 * q + 2]);
                    acc[4 * q + 3] = fmaf(wv.w, s, acc[4 * q + 3]);
                }
            }
        }
    }
#pragma unroll
    for (int o = 0; o < 64; o++) out[(size_t)o * HWN + pix] = acc[o] + bias[o];
}

// ---------------- launch ----------------
extern "C" void kernel_launch(void* const* d_in, const int* in_sizes, int n_in,
                              void* d_out, int out_size)
{
    (void)in_sizes; (void)n_in; (void)out_size;
    const float* feat_prev = (const float*)d_in[0];
    const float* feat_next = (const float*)d_in[1];
    const float* extra_prev = (const float*)d_in[2];
    const float* extra_next = (const float*)d_in[3];
    const float* flow_prev = (const float*)d_in[4];
    const float* flow_next = (const float*)d_in[5];
    // off1: 6..13, off2: 14..21
    const float* dcn1_w = (const float*)d_in[22];
    const float* dcn1_b = (const float*)d_in[23];
    const float* dcn2_w = (const float*)d_in[24];
    const float* dcn2_b = (const float*)d_in[25];
    const float* fus_w = (const float*)d_in[26];
    const float* fus_b = (const float*)d_in[27];
    float* out = (float*)d_out;

    float *t0, *t1, *c3, *cat, *wT;
    cudaGetSymbolAddress((void**)&t0, g_t0);
    cudaGetSymbolAddress((void**)&t1, g_t1);
    cudaGetSymbolAddress((void**)&c3, g_conv3);
    cudaGetSymbolAddress((void**)&cat, g_cat);
    cudaGetSymbolAddress((void**)&wT, g_wT);

    dim3 blk(128);
    dim3 g64(8, 16, 8);    // 64 output channels
    dim3 g216(8, 16, 27);  // 216 output channels

    for (int br = 0; br < 2; br++) {
        const float* feat = br == 0 ? feat_prev : feat_next;
        const float* extra = br == 0 ? extra_prev : extra_next;
        const float* flow = br == 0 ? flow_prev : flow_next;
        const float* w0 = (const float*)d_in[6 + 8 * br + 0];
        const float* b0 = (const float*)d_in[6 + 8 * br + 1];
        const float* w1 = (const float*)d_in[6 + 8 * br + 2];
        const float* b1 = (const float*)d_in[6 + 8 * br + 3];
        const float* w2 = (const float*)d_in[6 + 8 * br + 4];
        const float* b2 = (const float*)d_in[6 + 8 * br + 5];
        const float* w3 = (const float*)d_in[6 + 8 * br + 6];
        const float* b3 = (const float*)d_in[6 + 8 * br + 7];
        const float* dw = br == 0 ? dcn1_w : dcn2_w;
        const float* db = br == 0 ? dcn1_b : dcn2_b;
        float* catout = cat + (size_t)br * 64 * HWN;

        conv3x3_kernel<128, true><<<g64, blk>>>(extra, w0, b0, t0);
        conv3x3_kernel<64, true><<<g64, blk>>>(t0, w1, b1, t1);
        conv3x3_kernel<64, true><<<g64, blk>>>(t1, w2, b2, t0);
        conv3x3_kernel<64, false><<<g216, blk>>>(t0, w3, b3, c3);
        transpose_w_kernel<<<144, 256>>>(dw, wT);
        mdcn_kernel<<<dim3(8, 32), 256>>>(feat, c3, flow, wT, db, catout);
    }
    conv3x3_kernel<128, false><<<g64, blk>>>(cat, fus_w, fus_b, out);
}

// round 4
// speedup vs baseline: 1.3279x; 1.3279x over previous
#include <cuda_runtime.h>
#include <math.h>

#define HH 256
#define WW 256
#define HWN 65536
#define PW 264
#define PHh 258
#define PS (258 * 264)

// ---------------- scratch (device globals; no allocation allowed) ----------------
__device__ float g_pin[128 * PS];   // padded extra-feat input
__device__ float g_t0[64 * PS];
__device__ float g_t1[64 * PS];
__device__ float g_c3[216 * PS];    // conv4 raw output (padded layout, halo unused)
__device__ float g_cat[128 * PS];   // mdcn outputs (padded, halo zeroed)
__device__ float g_wT[9 * 64 * 64];

// ---------------- zero halo (rows 0/257 full, cols 0/257) ----------------
__global__ void zero_halo_kernel(float* __restrict__ buf, int C)
{
    int i = blockIdx.x * 256 + threadIdx.x;
    int n_per = 2 * PW + 2 * 256;  // 1040
    if (i >= C * n_per) return;
    int ch = i / n_per;
    int r = i - ch * n_per;
    float* p = buf + (size_t)ch * PS;
    if (r < PW) p[r] = 0.f;
    else if (r < 2 * PW) p[(size_t)257 * PW + (r - PW)] = 0.f;
    else if (r < 2 * PW + 256) p[(size_t)(r - 2 * PW + 1) * PW] = 0.f;
    else p[(size_t)(r - 2 * PW - 256 + 1) * PW + 257] = 0.f;
}

// ---------------- pad copy: [C,256,256] -> padded interior ----------------
__global__ void pad_kernel(const float* __restrict__ in, float* __restrict__ out, int C)
{
    int i = blockIdx.x * 256 + threadIdx.x;
    if (i >= C * HWN) return;
    int ch = i >> 16;
    int r = i & 65535;
    int y = r >> 8, x = r & 255;
    out[(size_t)ch * PS + (size_t)(y + 1) * PW + x + 1] = in[i];
}

// ---------------- direct 3x3 conv on padded input, no bounds checks ----------------
// Block 128 threads (8 x-groups x 16 rows). Tile 64x16. 8 couts/block.
// Each thread: 8 consecutive x-pixels x 8 couts = 64 accumulators, sliding 3x10 window.
template <int CIN, bool LRELU, bool PADOUT>
__global__ __launch_bounds__(128) void conv3x3_kernel(
    const float* __restrict__ in, const float* __restrict__ wgt,
    const float* __restrict__ bias, float* __restrict__ out)
{
    __shared__ float s_in[2][18][66];
    __shared__ float s_w[CIN][8][9];

    const int tid = threadIdx.x;
    const int txg = tid & 7;
    const int ty = tid >> 3;   // 0..15
    const int x0 = blockIdx.x * 64;
    const int y0 = blockIdx.y * 16;
    const int coB = blockIdx.z * 8;

    for (int i = tid; i < CIN * 8 * 9; i += 128) {
        int co = i / (CIN * 9);
        int r = i - co * (CIN * 9);
        int ci = r / 9;
        int k = r - ci * 9;
        s_w[ci][co][k] = wgt[(size_t)(coB + co) * (CIN * 9) + r];
    }
    for (int i = tid; i < 18 * 66; i += 128) {
        int r = i / 66, c = i - r * 66;
        s_in[0][r][c] = in[(size_t)(y0 + r) * PW + x0 + c];
    }
    __syncthreads();

    float acc[8][8];  // [cout][px]
#pragma unroll
    for (int o = 0; o < 8; o++)
#pragma unroll
        for (int p = 0; p < 8; p++) acc[o][p] = 0.f;

    const int xb = txg * 8;
    for (int ci = 0; ci < CIN; ci++) {
        const int pb = ci & 1;
        if (ci + 1 < CIN) {
            const float* ip = in + (size_t)(ci + 1) * PS;
            for (int i = tid; i < 18 * 66; i += 128) {
                int r = i / 66, c = i - r * 66;
                s_in[1 - pb][r][c] = ip[(size_t)(y0 + r) * PW + x0 + c];
            }
        }
        float v[3][10];
#pragma unroll
        for (int r = 0; r < 3; r++)
#pragma unroll
            for (int c = 0; c < 10; c++) v[r][c] = s_in[pb][ty + r][xb + c];

#pragma unroll
        for (int o = 0; o < 8; o++) {
            float wr[9];
#pragma unroll
            for (int k = 0; k < 9; k++) wr[k] = s_w[ci][o][k];
#pragma unroll
            for (int p = 0; p < 8; p++) {
                float a = acc[o][p];
                a = fmaf(v[0][p + 0], wr[0], a);
                a = fmaf(v[0][p + 1], wr[1], a);
                a = fmaf(v[0][p + 2], wr[2], a);
                a = fmaf(v[1][p + 0], wr[3], a);
                a = fmaf(v[1][p + 1], wr[4], a);
                a = fmaf(v[1][p + 2], wr[5], a);
                a = fmaf(v[2][p + 0], wr[6], a);
                a = fmaf(v[2][p + 1], wr[7], a);
                a = fmaf(v[2][p + 2], wr[8], a);
                acc[o][p] = a;
            }
        }
        __syncthreads();
    }

    const int oy = y0 + ty;
    const int ox = x0 + xb;
#pragma unroll
    for (int o = 0; o < 8; o++) {
        float bb = bias[coB + o];
#pragma unroll
        for (int p = 0; p < 8; p++) {
            float r = acc[o][p] + bb;
            if (LRELU) r = (r >= 0.f) ? r : 0.1f * r;
            if (PADOUT)
                out[(size_t)(coB + o) * PS + (size_t)(oy + 1) * PW + ox + 1 + p] = r;
            else
                out[(size_t)(coB + o) * HWN + (size_t)oy * WW + ox + p] = r;
        }
    }
}

// ---------------- weight transpose for mdcn: wT[k][cin][o] = w[o][cin][k] ----------
__global__ void transpose_w_kernel(const float* __restrict__ wsrc, float* __restrict__ wT)
{
    int i = blockIdx.x * 256 + threadIdx.x;
    if (i < 9 * 4096) {
        int k = i / 4096;
        int r = i - k * 4096;
        int ci = r >> 6;
        int o = r & 63;
        wT[i] = wsrc[(size_t)(o * 64 + ci) * 9 + k];
    }
}

__device__ __forceinline__ float fast_tanh(float x)
{
    x = fminf(fmaxf(x, -15.f), 15.f);
    float e = __expf(2.f * x);
    return (e - 1.f) / (e + 1.f);
}

// ---------------- modulated deformable conv (fused offset transform) --------------
// Block 128 threads (32x x 4y), one pixel/thread, 64 fp32 accumulators.
__global__ __launch_bounds__(128) void mdcn_kernel(
    const float* __restrict__ x,     // [64,256,256] feature (unpadded)
    const float* __restrict__ co,    // [216] padded planes: offset-net raw output
    const float* __restrict__ flow,  // [2,256,256]
    const float* __restrict__ wT,    // [9,64,64] (k,cin,o)
    const float* __restrict__ bias,  // [64]
    float* __restrict__ out)         // [64] padded planes
{
    __shared__ __align__(16) float s_w[4096];
    const int tid = threadIdx.x;
    const int px = blockIdx.x * 32 + (tid & 31);
    const int pyi = blockIdx.y * 4 + (tid >> 5);
    const int pix = pyi * WW + px;
    const int ppix = (pyi + 1) * PW + px + 1;

    const float f0 = flow[pix];
    const float f1 = flow[HWN + pix];

    float acc[64];
#pragma unroll
    for (int o = 0; o < 64; o++) acc[o] = 0.f;

#pragma unroll 1
    for (int k = 0; k < 9; k++) {
        __syncthreads();
        {
            const float4* src = reinterpret_cast<const float4*>(wT + (size_t)k * 4096);
            float4* dst = reinterpret_cast<float4*>(s_w);
            for (int i = tid; i < 1024; i += 128) dst[i] = src[i];
        }
        __syncthreads();
        const float kyf = (float)(k / 3 - 1);
        const float kxf = (float)(k % 3 - 1);
#pragma unroll 1
        for (int g = 0; g < 8; g++) {
            float oy = 10.f * fast_tanh(co[(size_t)(g * 18 + 2 * k) * PS + ppix]) + f1;
            float ox = 10.f * fast_tanh(co[(size_t)(g * 18 + 2 * k + 1) * PS + ppix]) + f0;
            float mr = co[(size_t)(144 + g * 9 + k) * PS + ppix];
            float mv = 1.f / (1.f + __expf(-mr));

            float pyf = (float)pyi + kyf + oy;
            float pxf = (float)px + kxf + ox;
            float y0f = floorf(pyf), x0f = floorf(pxf);
            float ly = pyf - y0f, lx = pxf - x0f;
            int iy0 = (int)y0f, ix0 = (int)x0f;
            int iy1 = iy0 + 1, ix1 = ix0 + 1;
            bool vy0 = (iy0 >= 0) & (iy0 < HH);
            bool vy1 = (iy1 >= 0) & (iy1 < HH);
            bool vx0 = (ix0 >= 0) & (ix0 < WW);
            bool vx1 = (ix1 >= 0) & (ix1 < WW);
            int cy0 = min(max(iy0, 0), HH - 1), cy1 = min(max(iy1, 0), HH - 1);
            int cx0 = min(max(ix0, 0), WW - 1), cx1 = min(max(ix1, 0), WW - 1);
            float w00 = (1.f - ly) * (1.f - lx) * mv;
            float w01 = (1.f - ly) * lx * mv;
            float w10 = ly * (1.f - lx) * mv;
            float w11 = ly * lx * mv;
            int i00 = cy0 * WW + cx0, i01 = cy0 * WW + cx1;
            int i10 = cy1 * WW + cx0, i11 = cy1 * WW + cx1;

#pragma unroll
            for (int c4 = 0; c4 < 2; c4++) {
                // batch 16 gathers (4 channels x 4 corners) for MLP
                float v00[4], v01[4], v10[4], v11[4];
#pragma unroll
                for (int j = 0; j < 4; j++) {
                    const float* xc = x + (size_t)(g * 8 + c4 * 4 + j) * HWN;
                    v00[j] = (vy0 && vx0) ? xc[i00] : 0.f;
                    v01[j] = (vy0 && vx1) ? xc[i01] : 0.f;
                    v10[j] = (vy1 && vx0) ? xc[i10] : 0.f;
                    v11[j] = (vy1 && vx1) ? xc[i11] : 0.f;
                }
#pragma unroll
                for (int j = 0; j < 4; j++) {
                    float s = v00[j] * w00 + v01[j] * w01 + v10[j] * w10 + v11[j] * w11;
                    const float4* wp =
                        reinterpret_cast<const float4*>(&s_w[(g * 8 + c4 * 4 + j) * 64]);
#pragma unroll
                    for (int q = 0; q < 16; q++) {
                        float4 wv = wp[q];
                        acc[4 * q + 0] = fmaf(wv.x, s, acc[4 * q + 0]);
                        acc[4 * q + 1] = fmaf(wv.y, s, acc[4 * q + 1]);
                        acc[4 * q + 2] = fmaf(wv.z, s, acc[4 * q + 2]);
                        acc[4 * q + 3] = fmaf(wv.w, s, acc[4 * q + 3]);
                    }
                }
            }
        }
    }
#pragma unroll
    for (int o = 0; o < 64; o++) out[(size_t)o * PS + ppix] = acc[o] + bias[o];
}

// ---------------- launch ----------------
extern "C" void kernel_launch(void* const* d_in, const int* in_sizes, int n_in,
                              void* d_out, int out_size)
{
    (void)in_sizes; (void)n_in; (void)out_size;
    const float* feat_prev = (const float*)d_in[0];
    const float* feat_next = (const float*)d_in[1];
    const float* extra_prev = (const float*)d_in[2];
    const float* extra_next = (const float*)d_in[3];
    const float* flow_prev = (const float*)d_in[4];
    const float* flow_next = (const float*)d_in[5];
    const float* dcn1_w = (const float*)d_in[22];
    const float* dcn1_b = (const float*)d_in[23];
    const float* dcn2_w = (const float*)d_in[24];
    const float* dcn2_b = (const float*)d_in[25];
    const float* fus_w = (const float*)d_in[26];
    const float* fus_b = (const float*)d_in[27];
    float* out = (float*)d_out;

    float *pin, *t0, *t1, *c3, *cat, *wT;
    cudaGetSymbolAddress((void**)&pin, g_pin);
    cudaGetSymbolAddress((void**)&t0, g_t0);
    cudaGetSymbolAddress((void**)&t1, g_t1);
    cudaGetSymbolAddress((void**)&c3, g_c3);
    cudaGetSymbolAddress((void**)&cat, g_cat);
    cudaGetSymbolAddress((void**)&wT, g_wT);

    // zero halos (interior never touches them; idempotent per replay)
    zero_halo_kernel<<<(128 * 1040 + 255) / 256, 256>>>(pin, 128);
    zero_halo_kernel<<<(64 * 1040 + 255) / 256, 256>>>(t0, 64);
    zero_halo_kernel<<<(64 * 1040 + 255) / 256, 256>>>(t1, 64);
    zero_halo_kernel<<<(128 * 1040 + 255) / 256, 256>>>(cat, 128);

    dim3 blk(128);
    dim3 g64(4, 16, 8);
    dim3 g216(4, 16, 27);

    for (int br = 0; br < 2; br++) {
        const float* feat = br == 0 ? feat_prev : feat_next;
        const float* extra = br == 0 ? extra_prev : extra_next;
        const float* flow = br == 0 ? flow_prev : flow_next;
        const float* w0 = (const float*)d_in[6 + 8 * br + 0];
        const float* b0 = (const float*)d_in[6 + 8 * br + 1];
        const float* w1 = (const float*)d_in[6 + 8 * br + 2];
        const float* b1 = (const float*)d_in[6 + 8 * br + 3];
        const float* w2 = (const float*)d_in[6 + 8 * br + 4];
        const float* b2 = (const float*)d_in[6 + 8 * br + 5];
        const float* w3 = (const float*)d_in[6 + 8 * br + 6];
        const float* b3 = (const float*)d_in[6 + 8 * br + 7];
        const float* dw = br == 0 ? dcn1_w : dcn2_w;
        const float* db = br == 0 ? dcn1_b : dcn2_b;

        pad_kernel<<<(128 * HWN + 255) / 256, 256>>>(extra, pin, 128);
        conv3x3_kernel<128, true, true><<<g64, blk>>>(pin, w0, b0, t0);
        conv3x3_kernel<64, true, true><<<g64, blk>>>(t0, w1, b1, t1);
        conv3x3_kernel<64, true, true><<<g64, blk>>>(t1, w2, b2, t0);
        conv3x3_kernel<64, false, true><<<g216, blk>>>(t0, w3, b3, c3);
        transpose_w_kernel<<<144, 256>>>(dw, wT);
        mdcn_kernel<<<dim3(8, 64), blk>>>(feat, c3, flow, wT, db, cat + (size_t)br * 64 * PS);
    }
    conv3x3_kernel<128, false, false><<<g64, blk>>>(cat, fus_w, fus_b, out);
}